// round 9
// baseline (speedup 1.0000x reference)
#include <cuda_runtime.h>
#include <cuda_bf16.h>
#include <math_constants.h>
#include <cstdint>

#define B_  16
#define C_  256
#define IC_ 32
#define M_  16384
#define TM2 256
#define TILES2 (M_/TM2)            // 64
#define RSQRT_IC 0.17677669529663687f

// ---------------- scratch (__device__ globals; no allocation allowed) -------
__device__ float d_g[(size_t)B_*IC_*M_];               // 33.5 MB  g_x (biased)
__device__ float d_partG[(size_t)B_*TILES2*IC_*IC_];   // per-tile t.t^T (4 MB)
__device__ float d_partS[(size_t)B_*TILES2*IC_];       // per-tile sum(t)
__device__ float d_partG2[(size_t)B_*8*IC_*IC_];       // stage-2 partials
__device__ float d_partS2[(size_t)B_*8*IC_];
__device__ float d_attn[(size_t)B_*IC_*IC_];           // softmax result
__device__ float d_weff[(size_t)B_*IC_*C_];            // w_w @ attn  [j][c]
// weights packed in mma.m16n8k16 B-fragment order (N=32 each):
//   theta: single bf16 round-to-nearest; g: hi(trunc)/lo split
__device__ __align__(16) unsigned short d_Bt [32*256];
__device__ __align__(16) unsigned short d_Bgh[32*256];
__device__ __align__(16) unsigned short d_Bgl[32*256];

// ---------------- helpers ----------------------------------------------------
__device__ __forceinline__ uint32_t smem_u32(const void* p) {
    uint32_t a;
    asm("{ .reg .u64 t; cvta.to.shared.u64 t, %1; cvt.u32.u64 %0, t; }" : "=r"(a) : "l"(p));
    return a;
}
#define CP_ASYNC16(dst, src) \
    asm volatile("cp.async.ca.shared.global [%0], [%1], 16;" :: "r"(dst), "l"(src))
#define CP_COMMIT() asm volatile("cp.async.commit_group;" ::: "memory")
#define CP_WAIT(n)  asm volatile("cp.async.wait_group %0;" :: "n"(n) : "memory")

__device__ __forceinline__ float4 ldcs4(const float* p) {
    float4 v;
    asm volatile("ld.global.cs.v4.f32 {%0,%1,%2,%3}, [%4];"
                 : "=f"(v.x), "=f"(v.y), "=f"(v.z), "=f"(v.w) : "l"(p));
    return v;
}
__device__ __forceinline__ void stcs4(float* p, float4 v) {
    asm volatile("st.global.cs.v4.f32 [%0], {%1,%2,%3,%4};"
                 :: "l"(p), "f"(v.x), "f"(v.y), "f"(v.z), "f"(v.w) : "memory");
}

__device__ __forceinline__ void mma_bf16(float* d, const uint32_t* a,
                                         uint32_t b0, uint32_t b1) {
    asm volatile(
        "mma.sync.aligned.m16n8k16.row.col.f32.bf16.bf16.f32 "
        "{%0,%1,%2,%3}, {%4,%5,%6,%7}, {%8,%9}, {%0,%1,%2,%3};"
        : "+f"(d[0]), "+f"(d[1]), "+f"(d[2]), "+f"(d[3])
        : "r"(a[0]), "r"(a[1]), "r"(a[2]), "r"(a[3]), "r"(b0), "r"(b1));
}

__device__ __forceinline__ void split_pack(float f0, float f1,
                                           uint32_t& hi, uint32_t& lo, uint32_t& rn) {
    uint32_t b0 = __float_as_uint(f0), b1 = __float_as_uint(f1);
    hi = __byte_perm(b0, b1, 0x7632);                 // trunc {hi16(f0), hi16(f1)}
    float l0 = f0 - __uint_as_float(b0 & 0xFFFF0000u);
    float l1 = f1 - __uint_as_float(b1 & 0xFFFF0000u);
    __nv_bfloat162 p = __floats2bfloat162_rn(l0, l1);
    lo = *reinterpret_cast<uint32_t*>(&p);
    __nv_bfloat162 q = __floats2bfloat162_rn(f0, f1);  // rn single for theta
    rn = *reinterpret_cast<uint32_t*>(&q);
}

// swizzled smem read: buffer is 16 channels x 32 floats, 16B units XORed by ch
__device__ __forceinline__ float ldsx(const float* buf, int ch, int m) {
    return buf[ch * 32 + ((((m >> 2) ^ (ch & 7)) << 2) | (m & 3))];
}

// ============================================================================
// k0: pack weights into N=32 B-fragment layouts.
// ============================================================================
__global__ void k0_prep(const float* __restrict__ g_w, const float* __restrict__ theta_w)
{
    int idx = blockIdx.x * 256 + threadIdx.x;    // 0..16383
    int n = idx >> 8, k = idx & 255;             // n 0..63
    int ks = k >> 4, kr = k & 15;
    int r = kr >> 3, ct = (kr & 7) >> 1, e = kr & 1;
    int nb = (n & 31) >> 3, lane = (n & 7) * 4 + ct;
    int us = ((((ks * 4 + nb) * 32 + lane) * 2 + r) << 1) | e;

    if (n < 32) {
        float wv = theta_w[n * C_ + k];
        d_Bt[us] = __bfloat16_as_ushort(__float2bfloat16(wv));   // rn
    } else {
        float wv = g_w[(n - 32) * C_ + k];
        uint32_t bits = __float_as_uint(wv);
        float hif = __uint_as_float(bits & 0xFFFF0000u);
        d_Bgh[us] = (unsigned short)(bits >> 16);                // trunc hi
        d_Bgl[us] = __bfloat16_as_ushort(__float2bfloat16(wv - hif));
    }
}

// ============================================================================
// k1: per (batch, 256-pixel tile): D[256 m][64 n] = X^T @ [theta;g]^T
//   Each warp owns 32 pixels (2 m-fragments); warp-private 3-stage cp.async.
// ============================================================================
__global__ __launch_bounds__(256, 2) void k1_proj(
    const float* __restrict__ x,
    const float* __restrict__ g_b, const float* __restrict__ theta_b)
{
    // per warp: 3 buffers x (16 ch x 32 floats swizzled) = 6144 B; 8 warps = 48 KB
    __shared__ __align__(16) float Xs[8][3][16 * 32];
    float* Ts = &Xs[0][0][0];                         // [256][36] after main loop

    const int t = threadIdx.x;
    const int w = t >> 5, lane = t & 31;
    const int gr = lane >> 2, ct = lane & 3;
    const int tile = blockIdx.x, b = blockIdx.y;
    const int mbase = tile * TM2;

    const float* xw = x + (size_t)b * C_ * M_ + mbase + 32 * w;
    const int srow = lane >> 3;                       // 0..3
    const int sseg = lane & 7;                        // 16B segment
    const uint32_t swb = smem_u32(&Xs[w][0][0]);

    float acc[16][4];
#pragma unroll
    for (int i = 0; i < 16; i++)
#pragma unroll
        for (int j = 0; j < 4; j++) acc[i][j] = 0.f;

    const uint2* Bt2  = (const uint2*)d_Bt;
    const uint2* Bgh2 = (const uint2*)d_Bgh;
    const uint2* Bgl2 = (const uint2*)d_Bgl;

    // ---- prologue: stage chunks 0,1 (16 channels x 128 B each)
#pragma unroll
    for (int pc = 0; pc < 2; pc++) {
        uint32_t dst = swb + (uint32_t)pc * 2048;
#pragma unroll
        for (int kk = 0; kk < 4; kk++) {
            int row = srow + kk * 4;
            CP_ASYNC16(dst + (uint32_t)(row * 128 + ((sseg ^ (row & 7)) << 4)),
                       xw + (size_t)(pc * 16 + row) * M_ + sseg * 4);
        }
        CP_COMMIT();
    }

#pragma unroll
    for (int ck = 0; ck < 16; ck++) {
        if (ck <= 14) { CP_WAIT(1); } else { CP_WAIT(0); }
        __syncwarp();

        const float* Xb = &Xs[w][ck % 3][0];
        const int kb = 2 * ct;

        uint2 bt[4], bh[4], bl[4];
#pragma unroll
        for (int nb = 0; nb < 4; nb++) {
            bt[nb] = __ldg(&Bt2 [(ck * 4 + nb) * 32 + lane]);
            bh[nb] = __ldg(&Bgh2[(ck * 4 + nb) * 32 + lane]);
            bl[nb] = __ldg(&Bgl2[(ck * 4 + nb) * 32 + lane]);
        }

#pragma unroll
        for (int mf = 0; mf < 2; mf++) {
            const int mo = mf * 16;
            float f00 = ldsx(Xb, kb + 0, gr + mo),      f01 = ldsx(Xb, kb + 1, gr + mo);
            float f10 = ldsx(Xb, kb + 0, gr + 8 + mo),  f11 = ldsx(Xb, kb + 1, gr + 8 + mo);
            float f20 = ldsx(Xb, kb + 8, gr + mo),      f21 = ldsx(Xb, kb + 9, gr + mo);
            float f30 = ldsx(Xb, kb + 8, gr + 8 + mo),  f31 = ldsx(Xb, kb + 9, gr + 8 + mo);
            uint32_t ahi[4], alo[4], arn[4];
            split_pack(f00, f01, ahi[0], alo[0], arn[0]);
            split_pack(f10, f11, ahi[1], alo[1], arn[1]);
            split_pack(f20, f21, ahi[2], alo[2], arn[2]);
            split_pack(f30, f31, ahi[3], alo[3], arn[3]);
#pragma unroll
            for (int nb = 0; nb < 4; nb++) {
                mma_bf16(acc[mf * 4 + nb],     arn, bt[nb].x, bt[nb].y);   // theta
                mma_bf16(acc[8 + mf * 4 + nb], ahi, bh[nb].x, bh[nb].y);   // g hh
                mma_bf16(acc[8 + mf * 4 + nb], ahi, bl[nb].x, bl[nb].y);   // g hl
                mma_bf16(acc[8 + mf * 4 + nb], alo, bh[nb].x, bh[nb].y);   // g lh
            }
        }

        if (ck + 2 < 16) {
            uint32_t dst = swb + (uint32_t)((ck + 2) % 3) * 2048;
#pragma unroll
            for (int kk = 0; kk < 4; kk++) {
                int row = srow + kk * 4;
                CP_ASYNC16(dst + (uint32_t)(row * 128 + ((sseg ^ (row & 7)) << 4)),
                           xw + (size_t)((ck + 2) * 16 + row) * M_ + sseg * 4);
            }
            CP_COMMIT();
        }
    }

    // ---- g -> d_g (gmem, +bias) straight from registers
#pragma unroll
    for (int mf = 0; mf < 2; mf++) {
#pragma unroll
        for (int nb = 0; nb < 4; nb++) {
            int n = nb * 8 + 2 * ct;
            int mloc = 32 * w + mf * 16 + gr;
            float gb0 = __ldg(&g_b[n]), gb1 = __ldg(&g_b[n + 1]);
            float* p0 = d_g + ((size_t)b * IC_ + n) * M_ + mbase;
            float* p1 = d_g + ((size_t)b * IC_ + n + 1) * M_ + mbase;
            const float* a = acc[8 + mf * 4 + nb];
            p0[mloc]     = a[0] + gb0;
            p1[mloc]     = a[1] + gb1;
            p0[mloc + 8] = a[2] + gb0;
            p1[mloc + 8] = a[3] + gb1;
        }
    }

    __syncthreads();   // everyone done with private buffers; Xs reusable as Ts

    // ---- theta -> Ts[256][36]
#pragma unroll
    for (int mf = 0; mf < 2; mf++) {
#pragma unroll
        for (int nb = 0; nb < 4; nb++) {
            int n = nb * 8 + 2 * ct;
            int mloc = 32 * w + mf * 16 + gr;
            float tb0 = __ldg(&theta_b[n]), tb1 = __ldg(&theta_b[n + 1]);
            const float* a = acc[mf * 4 + nb];
            Ts[mloc * 36 + n]           = a[0] + tb0;
            Ts[mloc * 36 + n + 1]       = a[1] + tb1;
            Ts[(mloc + 8) * 36 + n]     = a[2] + tb0;
            Ts[(mloc + 8) * 36 + n + 1] = a[3] + tb1;
        }
    }
    __syncthreads();

    // ---- partial Gram: warp w -> rows 4w..4w+3 (LDS.128 bcast), lane j -> col
    {
        const int j = lane;
        float gac[4] = {0.f, 0.f, 0.f, 0.f};
        float sac = 0.f;
#pragma unroll 4
        for (int m = 0; m < TM2; m++) {
            float4 tr = *(const float4*)(Ts + m * 36 + w * 4);   // broadcast
            float tj = Ts[m * 36 + j];                            // conflict-free
            gac[0] += tr.x * tj; gac[1] += tr.y * tj;
            gac[2] += tr.z * tj; gac[3] += tr.w * tj;
            if (w == 0) sac += tj;
        }
        float* pG = d_partG + (size_t)(b * TILES2 + tile) * IC_ * IC_;
#pragma unroll
        for (int ii = 0; ii < 4; ii++)
            pG[(w * 4 + ii) * IC_ + j] = gac[ii];
        if (w == 0)
            d_partS[(size_t)(b * TILES2 + tile) * IC_ + j] = sac;
    }
}

// ============================================================================
// k2a: stage-1 reduction of Gram partials (128 blocks; 8 tiles each)
// ============================================================================
__global__ __launch_bounds__(256) void k2a_reduce()
{
    const int seg = blockIdx.x, b = blockIdx.y, t = threadIdx.x;
    const float* p = d_partG + (size_t)(b * TILES2 + seg * 8) * IC_ * IC_;
#pragma unroll
    for (int e = t; e < IC_ * IC_; e += 256) {
        float s = 0.f;
#pragma unroll
        for (int tl = 0; tl < 8; tl++) s += p[(size_t)tl * IC_ * IC_ + e];
        d_partG2[(size_t)(b * 8 + seg) * IC_ * IC_ + e] = s;
    }
    if (t < IC_) {
        const float* q = d_partS + (size_t)(b * TILES2 + seg * 8) * IC_;
        float s = 0.f;
#pragma unroll
        for (int tl = 0; tl < 8; tl++) s += q[tl * IC_ + t];
        d_partS2[(size_t)(b * 8 + seg) * IC_ + t] = s;
    }
}

// ============================================================================
// k2b (one block per batch): final reduce, sigma, softmax -> d_attn
// ============================================================================
__global__ __launch_bounds__(256) void k2_attn()
{
    __shared__ float gram[IC_ * IC_];
    __shared__ float mu[IC_];
    const int t = threadIdx.x, b = blockIdx.x;

    for (int e = t; e < IC_ * IC_; e += 256) {
        float s = 0.f;
        const float* p = d_partG2 + (size_t)b * 8 * IC_ * IC_ + e;
#pragma unroll
        for (int tl = 0; tl < 8; tl++) s += p[(size_t)tl * IC_ * IC_];
        gram[e] = s;
    }
    if (t < IC_) {
        float s = 0.f;
        const float* p = d_partS2 + (size_t)b * 8 * IC_ + t;
#pragma unroll
        for (int tl = 0; tl < 8; tl++) s += p[tl * IC_];
        mu[t] = s * (1.0f / M_);
    }
    __syncthreads();

    if (t < IC_) {
        float row[IC_];
        float mx = -CUDART_INF_F;
#pragma unroll
        for (int jj = 0; jj < IC_; jj++) {
            float v = (gram[t * IC_ + jj] * (1.0f / M_) - mu[t] * mu[jj]) * RSQRT_IC;
            row[jj] = v; mx = fmaxf(mx, v);
        }
        float sum = 0.f;
#pragma unroll
        for (int jj = 0; jj < IC_; jj++) { row[jj] = __expf(row[jj] - mx); sum += row[jj]; }
        float inv = 1.0f / sum;
#pragma unroll
        for (int jj = 0; jj < IC_; jj++)
            d_attn[(size_t)b * IC_ * IC_ + t * IC_ + jj] = row[jj] * inv;
    }
}

// ============================================================================
// k4: weff[j][c] = sum_i w_w[c][i] * attn[i][j]   grid (2, B_), 128 threads
// ============================================================================
__global__ __launch_bounds__(128) void k4_weff(const float* __restrict__ w_w)
{
    __shared__ float attn[IC_ * IC_];
    const int t = threadIdx.x, cb = blockIdx.x, b = blockIdx.y;

    for (int e = t; e < IC_ * IC_; e += 128)
        attn[e] = d_attn[(size_t)b * IC_ * IC_ + e];
    __syncthreads();

    const int c = cb * 128 + t;
    float ww[IC_];
#pragma unroll
    for (int ii = 0; ii < IC_; ii += 4) {
        float4 v = __ldg((const float4*)(w_w + c * IC_ + ii));
        ww[ii] = v.x; ww[ii+1] = v.y; ww[ii+2] = v.z; ww[ii+3] = v.w;
    }
#pragma unroll
    for (int jj = 0; jj < IC_; jj++) {
        float s = 0.f;
#pragma unroll
        for (int ii = 0; ii < IC_; ii++) s += ww[ii] * attn[ii * IC_ + jj];
        d_weff[((size_t)b * IC_ + jj) * C_ + c] = s;
    }
}

// ============================================================================
// k3: out[b][c][m] = sum_j weff[j][c]*g[j][m] + w_b[c] + x[b][c][m]
//   256 thr, 4c x 4m per thread, c-block 128, m-tile 32; 5 CTAs/SM target.
// ============================================================================
__global__ __launch_bounds__(256, 5) void k3_out(
    const float* __restrict__ x, const float* __restrict__ w_b,
    float* __restrict__ out)
{
    __shared__ __align__(16) float gs[IC_ * 32];    // [j][m]   4 KB
    __shared__ __align__(16) float wT[IC_ * 128];   // [j][c]  16 KB

    const int t = threadIdx.x;
    const int tile = blockIdx.x, cb = blockIdx.y, b = blockIdx.z;
    const int mbase = tile * 32;
    const int cbase = cb * 128;

    {   // gs: 256 float4 (one per thread)
        int j = t >> 3, m4 = (t & 7) * 4;
        *(float4*)(gs + j * 32 + m4) =
            *(const float4*)(d_g + ((size_t)b * IC_ + j) * M_ + mbase + m4);
    }
#pragma unroll
    for (int k = 0; k < 4; k++) {                   // wT: 1024 float4
        int f = t + k * 256;
        int j = f >> 5, c4 = (f & 31) * 4;
        *(float4*)(wT + j * 128 + c4) =
            *(const float4*)(d_weff + ((size_t)b * IC_ + j) * C_ + cbase + c4);
    }
    __syncthreads();

    const int m0 = (t & 7) * 4, c0 = (t >> 3) * 4;
    float acc[4][4];
#pragma unroll
    for (int i = 0; i < 4; i++)
#pragma unroll
        for (int j = 0; j < 4; j++) acc[i][j] = 0.f;

#pragma unroll
    for (int i = 0; i < IC_; i++) {
        float4 gv = *(const float4*)(gs + i * 32 + m0);
        float4 w0 = *(const float4*)(wT + i * 128 + c0);
        acc[0][0] += w0.x * gv.x; acc[0][1] += w0.x * gv.y; acc[0][2] += w0.x * gv.z; acc[0][3] += w0.x * gv.w;
        acc[1][0] += w0.y * gv.x; acc[1][1] += w0.y * gv.y; acc[1][2] += w0.y * gv.z; acc[1][3] += w0.y * gv.w;
        acc[2][0] += w0.z * gv.x; acc[2][1] += w0.z * gv.y; acc[2][2] += w0.z * gv.z; acc[2][3] += w0.z * gv.w;
        acc[3][0] += w0.w * gv.x; acc[3][1] += w0.w * gv.y; acc[3][2] += w0.w * gv.z; acc[3][3] += w0.w * gv.w;
    }

    const size_t base = ((size_t)b * C_ + cbase + c0) * M_ + mbase + m0;
#pragma unroll
    for (int ii = 0; ii < 4; ii++) {
        float wb = __ldg(&w_b[cbase + c0 + ii]);
        float4 xv = ldcs4(x + base + (size_t)ii * M_);
        float4 o = make_float4(acc[ii][0] + wb + xv.x, acc[ii][1] + wb + xv.y,
                               acc[ii][2] + wb + xv.z, acc[ii][3] + wb + xv.w);
        stcs4(out + base + (size_t)ii * M_, o);
    }
}

// ============================================================================
extern "C" void kernel_launch(void* const* d_in, const int* in_sizes, int n_in,
                              void* d_out, int out_size)
{
    const float* x       = (const float*)d_in[0];
    const float* g_w     = (const float*)d_in[1];
    const float* g_b     = (const float*)d_in[2];
    const float* theta_w = (const float*)d_in[3];
    const float* theta_b = (const float*)d_in[4];
    const float* w_w     = (const float*)d_in[5];
    const float* w_b     = (const float*)d_in[6];
    float* out = (float*)d_out;

    k0_prep<<<64, 256>>>(g_w, theta_w);
    k1_proj<<<dim3(TILES2, B_), 256>>>(x, g_b, theta_b);
    k2a_reduce<<<dim3(8, B_), 256>>>();
    k2_attn<<<B_, 256>>>();
    k4_weff<<<dim3(2, B_), 128>>>(w_w);
    k3_out<<<dim3(M_ / 32, 2, B_), 256>>>(x, w_b, out);
}

// round 10
// speedup vs baseline: 1.1210x; 1.1210x over previous
#include <cuda_runtime.h>
#include <cuda_bf16.h>
#include <math_constants.h>
#include <cstdint>

#define B_  16
#define C_  256
#define IC_ 32
#define M_  16384
#define TM2 256
#define TILES2 (M_/TM2)            // 64
#define RSQRT_IC 0.17677669529663687f

// ---------------- scratch (__device__ globals; no allocation allowed) -------
__device__ float d_g[(size_t)B_*IC_*M_];               // 33.5 MB  g_x (biased)
__device__ float d_partG[(size_t)B_*TILES2*IC_*IC_];   // per-tile t.t^T (4 MB)
__device__ float d_partS[(size_t)B_*TILES2*IC_];       // per-tile sum(t)
__device__ float d_partG2[(size_t)B_*8*IC_*IC_];       // stage-2 partials
__device__ float d_partS2[(size_t)B_*8*IC_];
__device__ float d_attn[(size_t)B_*IC_*IC_];           // softmax result
__device__ float d_weff[(size_t)B_*IC_*C_];            // w_w @ attn  [j][c]
// weights packed in mma.m16n8k16 B-fragment order (N=32 each):
//   theta: single bf16 round-to-nearest; g: hi(trunc)/lo split
__device__ __align__(16) unsigned short d_Bt [32*256];
__device__ __align__(16) unsigned short d_Bgh[32*256];
__device__ __align__(16) unsigned short d_Bgl[32*256];

// ---------------- helpers ----------------------------------------------------
__device__ __forceinline__ uint32_t smem_u32(const void* p) {
    uint32_t a;
    asm("{ .reg .u64 t; cvta.to.shared.u64 t, %1; cvt.u32.u64 %0, t; }" : "=r"(a) : "l"(p));
    return a;
}
#define CP_ASYNC16(dst, src) \
    asm volatile("cp.async.ca.shared.global [%0], [%1], 16;" :: "r"(dst), "l"(src))
#define CP_COMMIT() asm volatile("cp.async.commit_group;" ::: "memory")
#define CP_WAIT(n)  asm volatile("cp.async.wait_group %0;" :: "n"(n) : "memory")

__device__ __forceinline__ void stcs4(float* p, float4 v) {
    asm volatile("st.global.cs.v4.f32 [%0], {%1,%2,%3,%4};"
                 :: "l"(p), "f"(v.x), "f"(v.y), "f"(v.z), "f"(v.w) : "memory");
}

__device__ __forceinline__ void mma_bf16(float* d, const uint32_t* a,
                                         uint32_t b0, uint32_t b1) {
    asm volatile(
        "mma.sync.aligned.m16n8k16.row.col.f32.bf16.bf16.f32 "
        "{%0,%1,%2,%3}, {%4,%5,%6,%7}, {%8,%9}, {%0,%1,%2,%3};"
        : "+f"(d[0]), "+f"(d[1]), "+f"(d[2]), "+f"(d[3])
        : "r"(a[0]), "r"(a[1]), "r"(a[2]), "r"(a[3]), "r"(b0), "r"(b1));
}

__device__ __forceinline__ void split_pack(float f0, float f1,
                                           uint32_t& hi, uint32_t& lo, uint32_t& rn) {
    uint32_t b0 = __float_as_uint(f0), b1 = __float_as_uint(f1);
    hi = __byte_perm(b0, b1, 0x7632);                 // trunc {hi16(f0), hi16(f1)}
    float l0 = f0 - __uint_as_float(b0 & 0xFFFF0000u);
    float l1 = f1 - __uint_as_float(b1 & 0xFFFF0000u);
    __nv_bfloat162 p = __floats2bfloat162_rn(l0, l1);
    lo = *reinterpret_cast<uint32_t*>(&p);
    __nv_bfloat162 q = __floats2bfloat162_rn(f0, f1);  // rn single for theta
    rn = *reinterpret_cast<uint32_t*>(&q);
}

// swizzled smem read: buffer is 16 channels x 32 floats, 16B units XORed by ch
__device__ __forceinline__ float ldsx(const float* buf, int ch, int m) {
    return buf[ch * 32 + ((((m >> 2) ^ (ch & 7)) << 2) | (m & 3))];
}

// ============================================================================
// k0: pack weights into N=32 B-fragment layouts.
// ============================================================================
__global__ void k0_prep(const float* __restrict__ g_w, const float* __restrict__ theta_w)
{
    int idx = blockIdx.x * 256 + threadIdx.x;    // 0..16383
    int n = idx >> 8, k = idx & 255;             // n 0..63
    int ks = k >> 4, kr = k & 15;
    int r = kr >> 3, ct = (kr & 7) >> 1, e = kr & 1;
    int nb = (n & 31) >> 3, lane = (n & 7) * 4 + ct;
    int us = ((((ks * 4 + nb) * 32 + lane) * 2 + r) << 1) | e;

    if (n < 32) {
        float wv = theta_w[n * C_ + k];
        d_Bt[us] = __bfloat16_as_ushort(__float2bfloat16(wv));   // rn
    } else {
        float wv = g_w[(n - 32) * C_ + k];
        uint32_t bits = __float_as_uint(wv);
        float hif = __uint_as_float(bits & 0xFFFF0000u);
        d_Bgh[us] = (unsigned short)(bits >> 16);                // trunc hi
        d_Bgl[us] = __bfloat16_as_ushort(__float2bfloat16(wv - hif));
    }
}

// ============================================================================
// k1: per (batch, 256-pixel tile): D[256 m][64 n] = X^T @ [theta;g]^T
//   Each warp owns 32 pixels (2 m-fragments); warp-private 3-stage cp.async.
// ============================================================================
__global__ __launch_bounds__(256, 2) void k1_proj(
    const float* __restrict__ x,
    const float* __restrict__ g_b, const float* __restrict__ theta_b)
{
    // per warp: 3 buffers x (16 ch x 32 floats swizzled) = 6144 B; 8 warps = 48 KB
    __shared__ __align__(16) float Xs[8][3][16 * 32];
    float* Ts = &Xs[0][0][0];                         // [256][36] after main loop

    const int t = threadIdx.x;
    const int w = t >> 5, lane = t & 31;
    const int gr = lane >> 2, ct = lane & 3;
    const int tile = blockIdx.x, b = blockIdx.y;
    const int mbase = tile * TM2;

    const float* xw = x + (size_t)b * C_ * M_ + mbase + 32 * w;
    const int srow = lane >> 3;                       // 0..3
    const int sseg = lane & 7;                        // 16B segment
    const uint32_t swb = smem_u32(&Xs[w][0][0]);

    float acc[16][4];
#pragma unroll
    for (int i = 0; i < 16; i++)
#pragma unroll
        for (int j = 0; j < 4; j++) acc[i][j] = 0.f;

    const uint2* Bt2  = (const uint2*)d_Bt;
    const uint2* Bgh2 = (const uint2*)d_Bgh;
    const uint2* Bgl2 = (const uint2*)d_Bgl;

    // ---- prologue: stage chunks 0,1 (16 channels x 128 B each)
#pragma unroll
    for (int pc = 0; pc < 2; pc++) {
        uint32_t dst = swb + (uint32_t)pc * 2048;
#pragma unroll
        for (int kk = 0; kk < 4; kk++) {
            int row = srow + kk * 4;
            CP_ASYNC16(dst + (uint32_t)(row * 128 + ((sseg ^ (row & 7)) << 4)),
                       xw + (size_t)(pc * 16 + row) * M_ + sseg * 4);
        }
        CP_COMMIT();
    }

#pragma unroll
    for (int ck = 0; ck < 16; ck++) {
        if (ck <= 14) { CP_WAIT(1); } else { CP_WAIT(0); }
        __syncwarp();

        const float* Xb = &Xs[w][ck % 3][0];
        const int kb = 2 * ct;

        uint2 bt[4], bh[4], bl[4];
#pragma unroll
        for (int nb = 0; nb < 4; nb++) {
            bt[nb] = __ldg(&Bt2 [(ck * 4 + nb) * 32 + lane]);
            bh[nb] = __ldg(&Bgh2[(ck * 4 + nb) * 32 + lane]);
            bl[nb] = __ldg(&Bgl2[(ck * 4 + nb) * 32 + lane]);
        }

#pragma unroll
        for (int mf = 0; mf < 2; mf++) {
            const int mo = mf * 16;
            float f00 = ldsx(Xb, kb + 0, gr + mo),      f01 = ldsx(Xb, kb + 1, gr + mo);
            float f10 = ldsx(Xb, kb + 0, gr + 8 + mo),  f11 = ldsx(Xb, kb + 1, gr + 8 + mo);
            float f20 = ldsx(Xb, kb + 8, gr + mo),      f21 = ldsx(Xb, kb + 9, gr + mo);
            float f30 = ldsx(Xb, kb + 8, gr + 8 + mo),  f31 = ldsx(Xb, kb + 9, gr + 8 + mo);
            uint32_t ahi[4], alo[4], arn[4];
            split_pack(f00, f01, ahi[0], alo[0], arn[0]);
            split_pack(f10, f11, ahi[1], alo[1], arn[1]);
            split_pack(f20, f21, ahi[2], alo[2], arn[2]);
            split_pack(f30, f31, ahi[3], alo[3], arn[3]);
#pragma unroll
            for (int nb = 0; nb < 4; nb++) {
                mma_bf16(acc[mf * 4 + nb],     arn, bt[nb].x, bt[nb].y);   // theta
                mma_bf16(acc[8 + mf * 4 + nb], ahi, bh[nb].x, bh[nb].y);   // g hh
                mma_bf16(acc[8 + mf * 4 + nb], ahi, bl[nb].x, bl[nb].y);   // g hl
                mma_bf16(acc[8 + mf * 4 + nb], alo, bh[nb].x, bh[nb].y);   // g lh
            }
        }

        if (ck + 2 < 16) {
            uint32_t dst = swb + (uint32_t)((ck + 2) % 3) * 2048;
#pragma unroll
            for (int kk = 0; kk < 4; kk++) {
                int row = srow + kk * 4;
                CP_ASYNC16(dst + (uint32_t)(row * 128 + ((sseg ^ (row & 7)) << 4)),
                           xw + (size_t)((ck + 2) * 16 + row) * M_ + sseg * 4);
            }
            CP_COMMIT();
        }
    }

    // ---- g -> d_g (gmem, +bias) straight from registers
#pragma unroll
    for (int mf = 0; mf < 2; mf++) {
#pragma unroll
        for (int nb = 0; nb < 4; nb++) {
            int n = nb * 8 + 2 * ct;
            int mloc = 32 * w + mf * 16 + gr;
            float gb0 = __ldg(&g_b[n]), gb1 = __ldg(&g_b[n + 1]);
            float* p0 = d_g + ((size_t)b * IC_ + n) * M_ + mbase;
            float* p1 = d_g + ((size_t)b * IC_ + n + 1) * M_ + mbase;
            const float* a = acc[8 + mf * 4 + nb];
            p0[mloc]     = a[0] + gb0;
            p1[mloc]     = a[1] + gb1;
            p0[mloc + 8] = a[2] + gb0;
            p1[mloc + 8] = a[3] + gb1;
        }
    }

    __syncthreads();   // everyone done with private buffers; Xs reusable as Ts

    // ---- theta -> Ts[256][36]
#pragma unroll
    for (int mf = 0; mf < 2; mf++) {
#pragma unroll
        for (int nb = 0; nb < 4; nb++) {
            int n = nb * 8 + 2 * ct;
            int mloc = 32 * w + mf * 16 + gr;
            float tb0 = __ldg(&theta_b[n]), tb1 = __ldg(&theta_b[n + 1]);
            const float* a = acc[mf * 4 + nb];
            Ts[mloc * 36 + n]           = a[0] + tb0;
            Ts[mloc * 36 + n + 1]       = a[1] + tb1;
            Ts[(mloc + 8) * 36 + n]     = a[2] + tb0;
            Ts[(mloc + 8) * 36 + n + 1] = a[3] + tb1;
        }
    }
    __syncthreads();

    // ---- partial Gram: warp w -> rows 4w..4w+3 (LDS.128 bcast), lane j -> col
    {
        const int j = lane;
        float gac[4] = {0.f, 0.f, 0.f, 0.f};
        float sac = 0.f;
#pragma unroll 4
        for (int m = 0; m < TM2; m++) {
            float4 tr = *(const float4*)(Ts + m * 36 + w * 4);   // broadcast
            float tj = Ts[m * 36 + j];                            // conflict-free
            gac[0] += tr.x * tj; gac[1] += tr.y * tj;
            gac[2] += tr.z * tj; gac[3] += tr.w * tj;
            if (w == 0) sac += tj;
        }
        float* pG = d_partG + (size_t)(b * TILES2 + tile) * IC_ * IC_;
#pragma unroll
        for (int ii = 0; ii < 4; ii++)
            pG[(w * 4 + ii) * IC_ + j] = gac[ii];
        if (w == 0)
            d_partS[(size_t)(b * TILES2 + tile) * IC_ + j] = sac;
    }
}

// ============================================================================
// k2a: stage-1 reduction of Gram partials (128 blocks; 8 tiles each)
// ============================================================================
__global__ __launch_bounds__(256) void k2a_reduce()
{
    const int seg = blockIdx.x, b = blockIdx.y, t = threadIdx.x;
    const float* p = d_partG + (size_t)(b * TILES2 + seg * 8) * IC_ * IC_;
#pragma unroll
    for (int e = t; e < IC_ * IC_; e += 256) {
        float s = 0.f;
#pragma unroll
        for (int tl = 0; tl < 8; tl++) s += p[(size_t)tl * IC_ * IC_ + e];
        d_partG2[(size_t)(b * 8 + seg) * IC_ * IC_ + e] = s;
    }
    if (t < IC_) {
        const float* q = d_partS + (size_t)(b * TILES2 + seg * 8) * IC_;
        float s = 0.f;
#pragma unroll
        for (int tl = 0; tl < 8; tl++) s += q[tl * IC_ + t];
        d_partS2[(size_t)(b * 8 + seg) * IC_ + t] = s;
    }
}

// ============================================================================
// k2b (one block per batch): final reduce, sigma, softmax -> d_attn
// ============================================================================
__global__ __launch_bounds__(256) void k2_attn()
{
    __shared__ float gram[IC_ * IC_];
    __shared__ float mu[IC_];
    const int t = threadIdx.x, b = blockIdx.x;

    for (int e = t; e < IC_ * IC_; e += 256) {
        float s = 0.f;
        const float* p = d_partG2 + (size_t)b * 8 * IC_ * IC_ + e;
#pragma unroll
        for (int tl = 0; tl < 8; tl++) s += p[(size_t)tl * IC_ * IC_];
        gram[e] = s;
    }
    if (t < IC_) {
        float s = 0.f;
        const float* p = d_partS2 + (size_t)b * 8 * IC_ + t;
#pragma unroll
        for (int tl = 0; tl < 8; tl++) s += p[tl * IC_];
        mu[t] = s * (1.0f / M_);
    }
    __syncthreads();

    if (t < IC_) {
        float row[IC_];
        float mx = -CUDART_INF_F;
#pragma unroll
        for (int jj = 0; jj < IC_; jj++) {
            float v = (gram[t * IC_ + jj] * (1.0f / M_) - mu[t] * mu[jj]) * RSQRT_IC;
            row[jj] = v; mx = fmaxf(mx, v);
        }
        float sum = 0.f;
#pragma unroll
        for (int jj = 0; jj < IC_; jj++) { row[jj] = __expf(row[jj] - mx); sum += row[jj]; }
        float inv = 1.0f / sum;
#pragma unroll
        for (int jj = 0; jj < IC_; jj++)
            d_attn[(size_t)b * IC_ * IC_ + t * IC_ + jj] = row[jj] * inv;
    }
}

// ============================================================================
// k4: weff[j][c] = sum_i w_w[c][i] * attn[i][j]   grid (2, B_), 128 threads
// ============================================================================
__global__ __launch_bounds__(128) void k4_weff(const float* __restrict__ w_w)
{
    __shared__ float attn[IC_ * IC_];
    const int t = threadIdx.x, cb = blockIdx.x, b = blockIdx.y;

    for (int e = t; e < IC_ * IC_; e += 128)
        attn[e] = d_attn[(size_t)b * IC_ * IC_ + e];
    __syncthreads();

    const int c = cb * 128 + t;
    float ww[IC_];
#pragma unroll
    for (int ii = 0; ii < IC_; ii += 4) {
        float4 v = __ldg((const float4*)(w_w + c * IC_ + ii));
        ww[ii] = v.x; ww[ii+1] = v.y; ww[ii+2] = v.z; ww[ii+3] = v.w;
    }
#pragma unroll
    for (int jj = 0; jj < IC_; jj++) {
        float s = 0.f;
#pragma unroll
        for (int ii = 0; ii < IC_; ii++) s += ww[ii] * attn[ii * IC_ + jj];
        d_weff[((size_t)b * IC_ + jj) * C_ + c] = s;
    }
}

// ============================================================================
// k3: out[b][c][m] = sum_j weff[j][c]*g[j][m] + w_b[c] + x[b][c][m]
//   (round-8 known-good: 32-pixel tile x all 256 channels; 8c x 4m; 4 CTAs/SM)
//   Only change: streaming stores for out (never re-read).
// ============================================================================
__global__ __launch_bounds__(256, 4) void k3_out(
    const float* __restrict__ x, const float* __restrict__ w_b,
    float* __restrict__ out)
{
    __shared__ __align__(16) float gs[IC_ * 32];    // [j][m]   4 KB
    __shared__ __align__(16) float wT[IC_ * C_];    // [j][c]  32 KB

    const int t = threadIdx.x;
    const int tile = blockIdx.x, b = blockIdx.y;
    const int mbase = tile * 32;

    {   // gs: 256 float4 (one per thread)
        int j = t >> 3, m4 = (t & 7) * 4;
        *(float4*)(gs + j * 32 + m4) =
            *(const float4*)(d_g + ((size_t)b * IC_ + j) * M_ + mbase + m4);
    }
#pragma unroll
    for (int k = 0; k < 8; k++) {                   // wT: 2048 float4
        int f = t + k * 256;
        int j = f >> 6, c4 = (f & 63) * 4;
        *(float4*)(wT + j * C_ + c4) =
            *(const float4*)(d_weff + ((size_t)b * IC_ + j) * C_ + c4);
    }
    __syncthreads();

    const int m0 = (t & 7) * 4, c0 = (t >> 3) * 8;
    float acc[8][4];
#pragma unroll
    for (int i = 0; i < 8; i++)
#pragma unroll
        for (int j = 0; j < 4; j++) acc[i][j] = 0.f;

#pragma unroll
    for (int i = 0; i < IC_; i++) {
        float4 gv = *(const float4*)(gs + i * 32 + m0);           // broadcast groups
        float4 w0 = *(const float4*)(wT + i * C_ + c0);           // broadcast
        float4 w1 = *(const float4*)(wT + i * C_ + c0 + 4);      // broadcast
        acc[0][0] += w0.x * gv.x; acc[0][1] += w0.x * gv.y; acc[0][2] += w0.x * gv.z; acc[0][3] += w0.x * gv.w;
        acc[1][0] += w0.y * gv.x; acc[1][1] += w0.y * gv.y; acc[1][2] += w0.y * gv.z; acc[1][3] += w0.y * gv.w;
        acc[2][0] += w0.z * gv.x; acc[2][1] += w0.z * gv.y; acc[2][2] += w0.z * gv.z; acc[2][3] += w0.z * gv.w;
        acc[3][0] += w0.w * gv.x; acc[3][1] += w0.w * gv.y; acc[3][2] += w0.w * gv.z; acc[3][3] += w0.w * gv.w;
        acc[4][0] += w1.x * gv.x; acc[4][1] += w1.x * gv.y; acc[4][2] += w1.x * gv.z; acc[4][3] += w1.x * gv.w;
        acc[5][0] += w1.y * gv.x; acc[5][1] += w1.y * gv.y; acc[5][2] += w1.y * gv.z; acc[5][3] += w1.y * gv.w;
        acc[6][0] += w1.z * gv.x; acc[6][1] += w1.z * gv.y; acc[6][2] += w1.z * gv.z; acc[6][3] += w1.z * gv.w;
        acc[7][0] += w1.w * gv.x; acc[7][1] += w1.w * gv.y; acc[7][2] += w1.w * gv.z; acc[7][3] += w1.w * gv.w;
    }

    const size_t base = ((size_t)b * C_ + c0) * M_ + mbase + m0;
#pragma unroll
    for (int ii = 0; ii < 8; ii++) {
        float wb = __ldg(&w_b[c0 + ii]);
        float4 xv = *(const float4*)(x + base + (size_t)ii * M_);
        float4 o = make_float4(acc[ii][0] + wb + xv.x, acc[ii][1] + wb + xv.y,
                               acc[ii][2] + wb + xv.z, acc[ii][3] + wb + xv.w);
        stcs4(out + base + (size_t)ii * M_, o);
    }
}

// ============================================================================
extern "C" void kernel_launch(void* const* d_in, const int* in_sizes, int n_in,
                              void* d_out, int out_size)
{
    const float* x       = (const float*)d_in[0];
    const float* g_w     = (const float*)d_in[1];
    const float* g_b     = (const float*)d_in[2];
    const float* theta_w = (const float*)d_in[3];
    const float* theta_b = (const float*)d_in[4];
    const float* w_w     = (const float*)d_in[5];
    const float* w_b     = (const float*)d_in[6];
    float* out = (float*)d_out;

    k0_prep<<<64, 256>>>(g_w, theta_w);
    k1_proj<<<dim3(TILES2, B_), 256>>>(x, g_b, theta_b);
    k2a_reduce<<<dim3(8, B_), 256>>>();
    k2_attn<<<B_, 256>>>();
    k4_weff<<<dim3(2, B_), 128>>>(w_w);
    k3_out<<<dim3(M_ / 32, B_), 256>>>(x, w_b, out);
}

// round 11
// speedup vs baseline: 1.1536x; 1.0290x over previous
#include <cuda_runtime.h>
#include <cuda_bf16.h>
#include <math_constants.h>
#include <cstdint>

#define B_  16
#define C_  256
#define IC_ 32
#define M_  16384
#define TM2 256
#define TILES2 (M_/TM2)            // 64
#define RSQRT_IC 0.17677669529663687f

// ---------------- scratch (__device__ globals; no allocation allowed) -------
__device__ float d_g[(size_t)B_*IC_*M_];               // 33.5 MB  g_x (biased)
__device__ float d_partG[(size_t)B_*TILES2*IC_*IC_];   // per-tile t.t^T (4 MB)
__device__ float d_partS[(size_t)B_*TILES2*IC_];       // per-tile sum(t)
__device__ float d_partG2[(size_t)B_*8*IC_*IC_];       // stage-2 partials
__device__ float d_partS2[(size_t)B_*8*IC_];
__device__ float d_attn[(size_t)B_*IC_*IC_];           // softmax result
__device__ float d_weff[(size_t)B_*IC_*C_];            // w_w @ attn  [j][c]
// weights packed in mma.m16n8k16 B-fragment order (N=32 each):
//   theta: single bf16 round-to-nearest; g: hi(trunc)/lo split
__device__ __align__(16) unsigned short d_Bt [32*256];
__device__ __align__(16) unsigned short d_Bgh[32*256];
__device__ __align__(16) unsigned short d_Bgl[32*256];

// ---------------- helpers ----------------------------------------------------
__device__ __forceinline__ uint32_t smem_u32(const void* p) {
    uint32_t a;
    asm("{ .reg .u64 t; cvta.to.shared.u64 t, %1; cvt.u32.u64 %0, t; }" : "=r"(a) : "l"(p));
    return a;
}
#define CP_ASYNC16(dst, src) \
    asm volatile("cp.async.ca.shared.global [%0], [%1], 16;" :: "r"(dst), "l"(src))
#define CP_COMMIT() asm volatile("cp.async.commit_group;" ::: "memory")
#define CP_WAIT(n)  asm volatile("cp.async.wait_group %0;" :: "n"(n) : "memory")

// ---- packed fp32 (Blackwell FFMA2; base sm_100-family PTX, not an 'a' feature)
__device__ __forceinline__ unsigned long long pk2(float a, float b) {
    unsigned long long r;
    asm("mov.b64 %0, {%1, %2};" : "=l"(r) : "f"(a), "f"(b));
    return r;
}
__device__ __forceinline__ void upk2(float& a, float& b, unsigned long long r) {
    asm("mov.b64 {%0, %1}, %2;" : "=f"(a), "=f"(b) : "l"(r));
}
__device__ __forceinline__ void ffma2(unsigned long long& d,
                                      unsigned long long a, unsigned long long b) {
    asm("fma.rn.f32x2 %0, %1, %2, %0;" : "+l"(d) : "l"(a), "l"(b));
}

__device__ __forceinline__ void mma_bf16(float* d, const uint32_t* a,
                                         uint32_t b0, uint32_t b1) {
    asm volatile(
        "mma.sync.aligned.m16n8k16.row.col.f32.bf16.bf16.f32 "
        "{%0,%1,%2,%3}, {%4,%5,%6,%7}, {%8,%9}, {%0,%1,%2,%3};"
        : "+f"(d[0]), "+f"(d[1]), "+f"(d[2]), "+f"(d[3])
        : "r"(a[0]), "r"(a[1]), "r"(a[2]), "r"(a[3]), "r"(b0), "r"(b1));
}

__device__ __forceinline__ void split_pack(float f0, float f1,
                                           uint32_t& hi, uint32_t& lo, uint32_t& rn) {
    uint32_t b0 = __float_as_uint(f0), b1 = __float_as_uint(f1);
    hi = __byte_perm(b0, b1, 0x7632);                 // trunc {hi16(f0), hi16(f1)}
    float l0 = f0 - __uint_as_float(b0 & 0xFFFF0000u);
    float l1 = f1 - __uint_as_float(b1 & 0xFFFF0000u);
    __nv_bfloat162 p = __floats2bfloat162_rn(l0, l1);
    lo = *reinterpret_cast<uint32_t*>(&p);
    __nv_bfloat162 q = __floats2bfloat162_rn(f0, f1);  // rn single for theta
    rn = *reinterpret_cast<uint32_t*>(&q);
}

// swizzled smem read: buffer is 16 channels x 32 floats, 16B units XORed by ch
__device__ __forceinline__ float ldsx(const float* buf, int ch, int m) {
    return buf[ch * 32 + ((((m >> 2) ^ (ch & 7)) << 2) | (m & 3))];
}

// ============================================================================
// k0: pack weights into N=32 B-fragment layouts.
// ============================================================================
__global__ void k0_prep(const float* __restrict__ g_w, const float* __restrict__ theta_w)
{
    int idx = blockIdx.x * 256 + threadIdx.x;    // 0..16383
    int n = idx >> 8, k = idx & 255;             // n 0..63
    int ks = k >> 4, kr = k & 15;
    int r = kr >> 3, ct = (kr & 7) >> 1, e = kr & 1;
    int nb = (n & 31) >> 3, lane = (n & 7) * 4 + ct;
    int us = ((((ks * 4 + nb) * 32 + lane) * 2 + r) << 1) | e;

    if (n < 32) {
        float wv = theta_w[n * C_ + k];
        d_Bt[us] = __bfloat16_as_ushort(__float2bfloat16(wv));   // rn
    } else {
        float wv = g_w[(n - 32) * C_ + k];
        uint32_t bits = __float_as_uint(wv);
        float hif = __uint_as_float(bits & 0xFFFF0000u);
        d_Bgh[us] = (unsigned short)(bits >> 16);                // trunc hi
        d_Bgl[us] = __bfloat16_as_ushort(__float2bfloat16(wv - hif));
    }
}

// ============================================================================
// k1: per (batch, 256-pixel tile): D[256 m][64 n] = X^T @ [theta;g]^T
//   Each warp owns 32 pixels (2 m-fragments); warp-private 3-stage cp.async.
// ============================================================================
__global__ __launch_bounds__(256, 2) void k1_proj(
    const float* __restrict__ x,
    const float* __restrict__ g_b, const float* __restrict__ theta_b)
{
    // per warp: 3 buffers x (16 ch x 32 floats swizzled) = 6144 B; 8 warps = 48 KB
    __shared__ __align__(16) float Xs[8][3][16 * 32];
    float* Ts = &Xs[0][0][0];                         // [256][36] after main loop

    const int t = threadIdx.x;
    const int w = t >> 5, lane = t & 31;
    const int gr = lane >> 2, ct = lane & 3;
    const int tile = blockIdx.x, b = blockIdx.y;
    const int mbase = tile * TM2;

    const float* xw = x + (size_t)b * C_ * M_ + mbase + 32 * w;
    const int srow = lane >> 3;                       // 0..3
    const int sseg = lane & 7;                        // 16B segment
    const uint32_t swb = smem_u32(&Xs[w][0][0]);

    float acc[16][4];
#pragma unroll
    for (int i = 0; i < 16; i++)
#pragma unroll
        for (int j = 0; j < 4; j++) acc[i][j] = 0.f;

    const uint2* Bt2  = (const uint2*)d_Bt;
    const uint2* Bgh2 = (const uint2*)d_Bgh;
    const uint2* Bgl2 = (const uint2*)d_Bgl;

    // ---- prologue: stage chunks 0,1 (16 channels x 128 B each)
#pragma unroll
    for (int pc = 0; pc < 2; pc++) {
        uint32_t dst = swb + (uint32_t)pc * 2048;
#pragma unroll
        for (int kk = 0; kk < 4; kk++) {
            int row = srow + kk * 4;
            CP_ASYNC16(dst + (uint32_t)(row * 128 + ((sseg ^ (row & 7)) << 4)),
                       xw + (size_t)(pc * 16 + row) * M_ + sseg * 4);
        }
        CP_COMMIT();
    }

#pragma unroll
    for (int ck = 0; ck < 16; ck++) {
        if (ck <= 14) { CP_WAIT(1); } else { CP_WAIT(0); }
        __syncwarp();

        const float* Xb = &Xs[w][ck % 3][0];
        const int kb = 2 * ct;

        uint2 bt[4], bh[4], bl[4];
#pragma unroll
        for (int nb = 0; nb < 4; nb++) {
            bt[nb] = __ldg(&Bt2 [(ck * 4 + nb) * 32 + lane]);
            bh[nb] = __ldg(&Bgh2[(ck * 4 + nb) * 32 + lane]);
            bl[nb] = __ldg(&Bgl2[(ck * 4 + nb) * 32 + lane]);
        }

#pragma unroll
        for (int mf = 0; mf < 2; mf++) {
            const int mo = mf * 16;
            float f00 = ldsx(Xb, kb + 0, gr + mo),      f01 = ldsx(Xb, kb + 1, gr + mo);
            float f10 = ldsx(Xb, kb + 0, gr + 8 + mo),  f11 = ldsx(Xb, kb + 1, gr + 8 + mo);
            float f20 = ldsx(Xb, kb + 8, gr + mo),      f21 = ldsx(Xb, kb + 9, gr + mo);
            float f30 = ldsx(Xb, kb + 8, gr + 8 + mo),  f31 = ldsx(Xb, kb + 9, gr + 8 + mo);
            uint32_t ahi[4], alo[4], arn[4];
            split_pack(f00, f01, ahi[0], alo[0], arn[0]);
            split_pack(f10, f11, ahi[1], alo[1], arn[1]);
            split_pack(f20, f21, ahi[2], alo[2], arn[2]);
            split_pack(f30, f31, ahi[3], alo[3], arn[3]);
#pragma unroll
            for (int nb = 0; nb < 4; nb++) {
                mma_bf16(acc[mf * 4 + nb],     arn, bt[nb].x, bt[nb].y);   // theta
                mma_bf16(acc[8 + mf * 4 + nb], ahi, bh[nb].x, bh[nb].y);   // g hh
                mma_bf16(acc[8 + mf * 4 + nb], ahi, bl[nb].x, bl[nb].y);   // g hl
                mma_bf16(acc[8 + mf * 4 + nb], alo, bh[nb].x, bh[nb].y);   // g lh
            }
        }

        if (ck + 2 < 16) {
            uint32_t dst = swb + (uint32_t)((ck + 2) % 3) * 2048;
#pragma unroll
            for (int kk = 0; kk < 4; kk++) {
                int row = srow + kk * 4;
                CP_ASYNC16(dst + (uint32_t)(row * 128 + ((sseg ^ (row & 7)) << 4)),
                           xw + (size_t)((ck + 2) * 16 + row) * M_ + sseg * 4);
            }
            CP_COMMIT();
        }
    }

    // ---- g -> d_g (gmem, +bias) straight from registers
#pragma unroll
    for (int mf = 0; mf < 2; mf++) {
#pragma unroll
        for (int nb = 0; nb < 4; nb++) {
            int n = nb * 8 + 2 * ct;
            int mloc = 32 * w + mf * 16 + gr;
            float gb0 = __ldg(&g_b[n]), gb1 = __ldg(&g_b[n + 1]);
            float* p0 = d_g + ((size_t)b * IC_ + n) * M_ + mbase;
            float* p1 = d_g + ((size_t)b * IC_ + n + 1) * M_ + mbase;
            const float* a = acc[8 + mf * 4 + nb];
            p0[mloc]     = a[0] + gb0;
            p1[mloc]     = a[1] + gb1;
            p0[mloc + 8] = a[2] + gb0;
            p1[mloc + 8] = a[3] + gb1;
        }
    }

    __syncthreads();   // everyone done with private buffers; Xs reusable as Ts

    // ---- theta -> Ts[256][36]
#pragma unroll
    for (int mf = 0; mf < 2; mf++) {
#pragma unroll
        for (int nb = 0; nb < 4; nb++) {
            int n = nb * 8 + 2 * ct;
            int mloc = 32 * w + mf * 16 + gr;
            float tb0 = __ldg(&theta_b[n]), tb1 = __ldg(&theta_b[n + 1]);
            const float* a = acc[mf * 4 + nb];
            Ts[mloc * 36 + n]           = a[0] + tb0;
            Ts[mloc * 36 + n + 1]       = a[1] + tb1;
            Ts[(mloc + 8) * 36 + n]     = a[2] + tb0;
            Ts[(mloc + 8) * 36 + n + 1] = a[3] + tb1;
        }
    }
    __syncthreads();

    // ---- partial Gram (FFMA2): warp w -> rows 4w..4w+3, lane j -> column j
    {
        const int j = lane;
        unsigned long long gac2[2] = {0ull, 0ull};    // {r0,r1},{r2,r3}
        float sac = 0.f;
#pragma unroll 4
        for (int m = 0; m < TM2; m++) {
            float4 tr = *(const float4*)(Ts + m * 36 + w * 4);   // broadcast
            float tj = Ts[m * 36 + j];                            // conflict-free
            unsigned long long tjp = pk2(tj, tj);
            ffma2(gac2[0], pk2(tr.x, tr.y), tjp);
            ffma2(gac2[1], pk2(tr.z, tr.w), tjp);
            if (w == 0) sac += tj;
        }
        float gac[4];
        upk2(gac[0], gac[1], gac2[0]);
        upk2(gac[2], gac[3], gac2[1]);
        float* pG = d_partG + (size_t)(b * TILES2 + tile) * IC_ * IC_;
#pragma unroll
        for (int ii = 0; ii < 4; ii++)
            pG[(w * 4 + ii) * IC_ + j] = gac[ii];
        if (w == 0)
            d_partS[(size_t)(b * TILES2 + tile) * IC_ + j] = sac;
    }
}

// ============================================================================
// k2a: stage-1 reduction of Gram partials (128 blocks; 8 tiles each)
// ============================================================================
__global__ __launch_bounds__(256) void k2a_reduce()
{
    const int seg = blockIdx.x, b = blockIdx.y, t = threadIdx.x;
    const float* p = d_partG + (size_t)(b * TILES2 + seg * 8) * IC_ * IC_;
#pragma unroll
    for (int e = t; e < IC_ * IC_; e += 256) {
        float s = 0.f;
#pragma unroll
        for (int tl = 0; tl < 8; tl++) s += p[(size_t)tl * IC_ * IC_ + e];
        d_partG2[(size_t)(b * 8 + seg) * IC_ * IC_ + e] = s;
    }
    if (t < IC_) {
        const float* q = d_partS + (size_t)(b * TILES2 + seg * 8) * IC_;
        float s = 0.f;
#pragma unroll
        for (int tl = 0; tl < 8; tl++) s += q[tl * IC_ + t];
        d_partS2[(size_t)(b * 8 + seg) * IC_ + t] = s;
    }
}

// ============================================================================
// k2b (one block per batch): final reduce, sigma, softmax -> d_attn
// ============================================================================
__global__ __launch_bounds__(256) void k2_attn()
{
    __shared__ float gram[IC_ * IC_];
    __shared__ float mu[IC_];
    const int t = threadIdx.x, b = blockIdx.x;

    for (int e = t; e < IC_ * IC_; e += 256) {
        float s = 0.f;
        const float* p = d_partG2 + (size_t)b * 8 * IC_ * IC_ + e;
#pragma unroll
        for (int tl = 0; tl < 8; tl++) s += p[(size_t)tl * IC_ * IC_];
        gram[e] = s;
    }
    if (t < IC_) {
        float s = 0.f;
        const float* p = d_partS2 + (size_t)b * 8 * IC_ + t;
#pragma unroll
        for (int tl = 0; tl < 8; tl++) s += p[tl * IC_];
        mu[t] = s * (1.0f / M_);
    }
    __syncthreads();

    if (t < IC_) {
        float row[IC_];
        float mx = -CUDART_INF_F;
#pragma unroll
        for (int jj = 0; jj < IC_; jj++) {
            float v = (gram[t * IC_ + jj] * (1.0f / M_) - mu[t] * mu[jj]) * RSQRT_IC;
            row[jj] = v; mx = fmaxf(mx, v);
        }
        float sum = 0.f;
#pragma unroll
        for (int jj = 0; jj < IC_; jj++) { row[jj] = __expf(row[jj] - mx); sum += row[jj]; }
        float inv = 1.0f / sum;
#pragma unroll
        for (int jj = 0; jj < IC_; jj++)
            d_attn[(size_t)b * IC_ * IC_ + t * IC_ + jj] = row[jj] * inv;
    }
}

// ============================================================================
// k4: weff[j][c] = sum_i w_w[c][i] * attn[i][j]   grid (2, B_), 128 threads
// ============================================================================
__global__ __launch_bounds__(128) void k4_weff(const float* __restrict__ w_w)
{
    __shared__ float attn[IC_ * IC_];
    const int t = threadIdx.x, cb = blockIdx.x, b = blockIdx.y;

    for (int e = t; e < IC_ * IC_; e += 128)
        attn[e] = d_attn[(size_t)b * IC_ * IC_ + e];
    __syncthreads();

    const int c = cb * 128 + t;
    float ww[IC_];
#pragma unroll
    for (int ii = 0; ii < IC_; ii += 4) {
        float4 v = __ldg((const float4*)(w_w + c * IC_ + ii));
        ww[ii] = v.x; ww[ii+1] = v.y; ww[ii+2] = v.z; ww[ii+3] = v.w;
    }
#pragma unroll
    for (int jj = 0; jj < IC_; jj++) {
        float s = 0.f;
#pragma unroll
        for (int ii = 0; ii < IC_; ii++) s += ww[ii] * attn[ii * IC_ + jj];
        d_weff[((size_t)b * IC_ + jj) * C_ + c] = s;
    }
}

// ============================================================================
// k3: out[b][c][m] = sum_j weff[j][c]*g[j][m] + w_b[c] + x[b][c][m]
//   Round-8 shape (32-pixel tile x all 256 channels; 8c x 4m; 4 CTAs/SM),
//   inner loop rewritten with packed fp32 FFMA2: acc pairs over adjacent c,
//   weight pairs come directly from wT LDS.128 (no splat).
// ============================================================================
__global__ __launch_bounds__(256, 4) void k3_out(
    const float* __restrict__ x, const float* __restrict__ w_b,
    float* __restrict__ out)
{
    __shared__ __align__(16) float gs[IC_ * 32];    // [j][m]   4 KB
    __shared__ __align__(16) float wT[IC_ * C_];    // [j][c]  32 KB

    const int t = threadIdx.x;
    const int tile = blockIdx.x, b = blockIdx.y;
    const int mbase = tile * 32;

    {   // gs: 256 float4 (one per thread)
        int j = t >> 3, m4 = (t & 7) * 4;
        *(float4*)(gs + j * 32 + m4) =
            *(const float4*)(d_g + ((size_t)b * IC_ + j) * M_ + mbase + m4);
    }
#pragma unroll
    for (int k = 0; k < 8; k++) {                   // wT: 2048 float4
        int f = t + k * 256;
        int j = f >> 6, c4 = (f & 63) * 4;
        *(float4*)(wT + j * C_ + c4) =
            *(const float4*)(d_weff + ((size_t)b * IC_ + j) * C_ + c4);
    }
    __syncthreads();

    const int m0 = (t & 7) * 4, c0 = (t >> 3) * 8;
    // acc2[cp*4 + mm] = {out(c0+2cp, m0+mm), out(c0+2cp+1, m0+mm)}
    unsigned long long acc2[16];
#pragma unroll
    for (int i = 0; i < 16; i++) acc2[i] = 0ull;

#pragma unroll
    for (int i = 0; i < IC_; i++) {
        float4 gv = *(const float4*)(gs + i * 32 + m0);           // broadcast groups
        float4 w0 = *(const float4*)(wT + i * C_ + c0);           // broadcast
        float4 w1 = *(const float4*)(wT + i * C_ + c0 + 4);      // broadcast
        unsigned long long wp0 = pk2(w0.x, w0.y);
        unsigned long long wp1 = pk2(w0.z, w0.w);
        unsigned long long wp2 = pk2(w1.x, w1.y);
        unsigned long long wp3 = pk2(w1.z, w1.w);
        float gvf[4] = {gv.x, gv.y, gv.z, gv.w};
#pragma unroll
        for (int mm = 0; mm < 4; mm++) {
            unsigned long long gsp = pk2(gvf[mm], gvf[mm]);
            ffma2(acc2[0 * 4 + mm], wp0, gsp);
            ffma2(acc2[1 * 4 + mm], wp1, gsp);
            ffma2(acc2[2 * 4 + mm], wp2, gsp);
            ffma2(acc2[3 * 4 + mm], wp3, gsp);
        }
    }

    const size_t base = ((size_t)b * C_ + c0) * M_ + mbase + m0;
#pragma unroll
    for (int cp = 0; cp < 4; cp++) {
        float a0[4], a1[4];
#pragma unroll
        for (int mm = 0; mm < 4; mm++)
            upk2(a0[mm], a1[mm], acc2[cp * 4 + mm]);

        int ii0 = 2 * cp, ii1 = 2 * cp + 1;
        float wb0 = __ldg(&w_b[c0 + ii0]);
        float4 xv0 = *(const float4*)(x + base + (size_t)ii0 * M_);
        float4 o0 = make_float4(a0[0] + wb0 + xv0.x, a0[1] + wb0 + xv0.y,
                                a0[2] + wb0 + xv0.z, a0[3] + wb0 + xv0.w);
        *(float4*)(out + base + (size_t)ii0 * M_) = o0;

        float wb1 = __ldg(&w_b[c0 + ii1]);
        float4 xv1 = *(const float4*)(x + base + (size_t)ii1 * M_);
        float4 o1 = make_float4(a1[0] + wb1 + xv1.x, a1[1] + wb1 + xv1.y,
                                a1[2] + wb1 + xv1.z, a1[3] + wb1 + xv1.w);
        *(float4*)(out + base + (size_t)ii1 * M_) = o1;
    }
}

// ============================================================================
extern "C" void kernel_launch(void* const* d_in, const int* in_sizes, int n_in,
                              void* d_out, int out_size)
{
    const float* x       = (const float*)d_in[0];
    const float* g_w     = (const float*)d_in[1];
    const float* g_b     = (const float*)d_in[2];
    const float* theta_w = (const float*)d_in[3];
    const float* theta_b = (const float*)d_in[4];
    const float* w_w     = (const float*)d_in[5];
    const float* w_b     = (const float*)d_in[6];
    float* out = (float*)d_out;

    k0_prep<<<64, 256>>>(g_w, theta_w);
    k1_proj<<<dim3(TILES2, B_), 256>>>(x, g_b, theta_b);
    k2a_reduce<<<dim3(8, B_), 256>>>();
    k2_attn<<<B_, 256>>>();
    k4_weff<<<dim3(2, B_), 128>>>(w_w);
    k3_out<<<dim3(M_ / 32, B_), 256>>>(x, w_b, out);
}